// round 11
// baseline (speedup 1.0000x reference)
#include <cuda_runtime.h>
#include <float.h>

// ROI max pooling, exact integer-bin partition (matches reference):
//   cell (py,px) of roi (y0,x0,h,w) covers rows [y0 + py*h/7, y0 + (py+1)*h/7)
//   and cols [x0 + px*w/7, x0 + (px+1)*w/7). h,w >= 7 so cells are non-empty.
//
// Shapes: feature_map [B=2, H=38, W=38, C=512] f32, rois [B=2, N=64, 4] i32,
// out [B, N, 7, 7, C] f32.
//
// R9 -> R10: residency-bound (occ 32% = ~20 warps; 1-warp blocks cap at 32
// blocks/SM, 72 regs caps at 28 warps). 128-thr blocks of 4 INDEPENDENT
// warps (warp w handles unit blockIdx*4+w; no smem, no sync) remove the
// block cap; 4-pixel unroll (8 in-flight LDG.128, R4-proven sufficient MLP)
// cuts regs to lift the reg-file warp cap.

#define H_DIM 38
#define W_DIM 38
#define C4 128           // C/4 float4 groups per pixel
#define POOL 7
#define UNITS (128 * POOL * POOL * 2)   // (B*N) * 49 cells * 2 channel halves

__device__ __forceinline__ void fmax4(float4& m, const float4 v) {
    m.x = fmaxf(m.x, v.x);
    m.y = fmaxf(m.y, v.y);
    m.z = fmaxf(m.z, v.z);
    m.w = fmaxf(m.w, v.w);
}

__global__ __launch_bounds__(128) void roi_pool_kernel(
    const float4* __restrict__ fm,   // [B, H, W, C/4] as float4
    const int*    __restrict__ rois, // [B*N, 4] (y, x, h, w)
    float4*       __restrict__ out,  // [B*N, 49, C/4] as float4
    int n_per_b)                     // N (rois per batch)
{
    // unit = cell * 2 + channel_half; one warp per unit, warps independent
    const int unit = blockIdx.x * 4 + (threadIdx.x >> 5);
    const int lane = threadIdx.x & 31;

    const int half = unit & 1;
    const int cell = unit >> 1;         // roi*49 + py*7 + px
    const int px   = cell % POOL;
    const int py   = (cell / POOL) % POOL;
    const int roi  = cell / (POOL * POOL);
    const int b    = roi / n_per_b;

    const int4 r = __ldg((const int4*)(rois + roi * 4));
    const int y0 = r.x, x0 = r.y, h = r.z, w = r.w;

    const int ys = y0 + (py * h) / POOL;
    const int ye = y0 + ((py + 1) * h) / POOL;
    const int xs = x0 + (px * w) / POOL;
    const int xe = x0 + ((px + 1) * w) / POOL;
    const int cw   = xe - xs;           // 1..6
    const int npix = cw * (ye - ys);    // 1..36

    // exact floor(idx/cw) for idx < 36, cw <= 6: magic = ceil(2^16/cw)
    const unsigned magic = (65536u + (unsigned)cw - 1u) / (unsigned)cw;

    // channel half: slots [half*64, half*64+64); thread owns c and c+32
    const int c = (half << 6) + lane;
    const float4* base = fm + (((size_t)b * H_DIM + ys) * W_DIM + xs) * C4 + c;

    float4 m0 = make_float4(-FLT_MAX, -FLT_MAX, -FLT_MAX, -FLT_MAX);
    float4 m1 = m0;

    const int last = npix - 1;

    for (int pbase = 0; pbase < npix; pbase += 4) {
        const float4* p[4];
#pragma unroll
        for (int k = 0; k < 4; ++k) {
            int idx = pbase + k;
            idx = idx < last ? idx : last;          // clamp: dup of last pixel
            const int dy = (int)(((unsigned)idx * magic) >> 16);
            const int dx = idx - dy * cw;
            p[k] = base + (size_t)(dy * W_DIM + dx) * C4;
        }
        float4 v0[4], v1[4];
#pragma unroll
        for (int k = 0; k < 4; ++k) {               // 8 independent LDG.128
            v0[k] = __ldg(p[k]);
            v1[k] = __ldg(p[k] + 32);
        }
#pragma unroll
        for (int k = 0; k < 4; ++k) {
            fmax4(m0, v0[k]);
            fmax4(m1, v1[k]);
        }
    }

    float4* o = out + (size_t)cell * C4 + c;
    o[0]  = m0;
    o[32] = m1;
}

extern "C" void kernel_launch(void* const* d_in, const int* in_sizes, int n_in,
                              void* d_out, int out_size) {
    const float4* fm   = (const float4*)d_in[0];
    const int*    rois = (const int*)d_in[1];
    float4*       out  = (float4*)d_out;

    const int n_rois  = in_sizes[1] / 4;     // B*N = 128
    const int B       = 2;                   // fixed per problem shapes
    const int n_per_b = n_rois / B;          // N = 64

    const int n_units = n_rois * POOL * POOL * 2;   // 12544
    roi_pool_kernel<<<n_units / 4, 128>>>(fm, rois, out, n_per_b);
}